// round 5
// baseline (speedup 1.0000x reference)
#include <cuda_runtime.h>

// Problem: volume [40,40,40,32] f32, M [32,32], P [32,32] -> Nk [59319,32]
//   b = (k1*39 + k2)*39 + k3
//   Nk[b,i] = sum_j x[b,j] * P[i,j] * cos(k1*a_ij) * cos(k2*a_ij) * cos(k3*a_ij)
//   a_ij = 2pi/(i*32+j+2),  x = (2x2x2 mean pool) @ M^T
#define NP   39
#define PI2F 6.2831853071795864769f

typedef unsigned long long ull;

__device__ float g_tab[39 * 1024];   // tab[k][j*32 + i] = cos(k * 2pi/(i*32+j+2))

// ---- f32x2 packed math (sm_103a) ------------------------------------------
__device__ __forceinline__ ull f2_mul(ull a, ull b) {
    ull d; asm("mul.rn.f32x2 %0, %1, %2;" : "=l"(d) : "l"(a), "l"(b)); return d;
}
__device__ __forceinline__ ull f2_fma(ull a, ull b, ull c) {
    ull d; asm("fma.rn.f32x2 %0, %1, %2, %3;" : "=l"(d) : "l"(a), "l"(b), "l"(c)); return d;
}
__device__ __forceinline__ ull f2_add(ull a, ull b) {
    ull d; asm("add.rn.f32x2 %0, %1, %2;" : "=l"(d) : "l"(a), "l"(b)); return d;
}
__device__ __forceinline__ ull f2_pack(float x) {
    ull d; asm("mov.b64 %0, {%1, %1};" : "=l"(d) : "f"(x)); return d;
}
__device__ __forceinline__ float2 f2_unpack(ull v) {
    float2 r; asm("mov.b64 {%0, %1}, %2;" : "=f"(r.x), "=f"(r.y) : "l"(v)); return r;
}

// ---------------------------------------------------------------------------
// Kernel 0: cos table via Chebyshev recurrence. grid 4 x 256.
// ---------------------------------------------------------------------------
__global__ void k_pre() {
    int t = blockIdx.x * 256 + threadIdx.x;   // t = j*32 + i
    int i = t & 31, j = t >> 5;
    float a  = PI2F / (float)(i * 32 + j + 2);
    float c1 = cosf(a);
    float twoc = 2.0f * c1;
    float cm2 = 1.0f, cm1 = c1;
    g_tab[t]        = 1.0f;
    g_tab[1024 + t] = c1;
#pragma unroll
    for (int k = 2; k < 39; k++) {
        float ck = twoc * cm1 - cm2;
        g_tab[k * 1024 + t] = ck;
        cm2 = cm1; cm1 = ck;
    }
}

// ---------------------------------------------------------------------------
// Fused kernel: pooling + x-matvec + main contraction.
// grid (10, 39): blockIdx.x = k2 tile of 4 (c), blockIdx.y = k1. 320 threads.
// Main loop: tid = jg*160 + k3p*8 + iq ; jg in {0,1} splits j (16 each),
// thread outputs 4(c) x 2(k3) x 4(i); group-1 partials reduced via smem.
// ---------------------------------------------------------------------------
// Shared memory float offsets (dynamic, 26672 floats = 104.2 KB):
#define S_VOL   0        // 12800   vol rows [10][1280]   (dead after pooling)
#define S_A     0        // 4096    A[c][j*32+i]          (overlaps vol)
#define S_PART  4096     // 5440 fl (2720 ull, stride 17) (overlaps vol)
#define S_X     12800    // 5120    x[c][j*40 + k3]
#define S_POOL  17920    // 5616    pooled[c][k3*36 + ch]
#define S_PS    23536    // 1056    P padded [i*33 + j]
#define S_MS    24592    // 1056    M padded [j*33 + l]
#define S_MT    25648    // 1024    MT[l*32 + j]
#define SMEM_FLOATS 26672

__global__ void __launch_bounds__(320) k_fused(
    const float* __restrict__ vol, const float* __restrict__ M,
    const float* __restrict__ P, float* __restrict__ out)
{
    extern __shared__ float sm[];
    const int k1  = blockIdx.y;
    const int k2b = blockIdx.x * 4;
    const int tid = threadIdx.x;

    // -------- Phase A: stage volume rows, M, P; zero x_s --------
    // 10 rows: dh = dd*5 + hh; global row (k1+dd)*40 + min(k2b+hh, 39)
    for (int f4 = tid; f4 < 3200; f4 += 320) {
        int dh = f4 / 320;
        int r  = f4 - dh * 320;
        int dd = dh / 5, hh = dh - dd * 5;
        int k2r = k2b + hh; if (k2r > 39) k2r = 39;
        ((float4*)(sm + S_VOL))[dh * 320 + r] =
            ((const float4*)vol)[((k1 + dd) * 40 + k2r) * 320 + r];
    }
    for (int g = tid; g < 1024; g += 320) {
        sm[S_PS + (g >> 5) * 33 + (g & 31)] = P[g];
        sm[S_MS + (g >> 5) * 33 + (g & 31)] = M[g];
    }
    for (int q = tid; q < 1280; q += 320)
        ((float4*)(sm + S_X))[q] = make_float4(0.f, 0.f, 0.f, 0.f);
    __syncthreads();

    // -------- Phase B: pooling (+ MT transpose) --------
    // pooled[c][k3][ch] = mean of vol[(dd, c+hh2, k3+ww)], float4 over ch
    for (int p4 = tid; p4 < 1248; p4 += 320) {
        int c   = p4 / 312;
        int rem = p4 - c * 312;
        int k3  = rem >> 3;
        int cq  = rem & 7;
        float4 s = make_float4(0.f, 0.f, 0.f, 0.f);
#pragma unroll
        for (int dd = 0; dd < 2; dd++)
#pragma unroll
            for (int hh2 = 0; hh2 < 2; hh2++)
#pragma unroll
                for (int ww = 0; ww < 2; ww++) {
                    float4 v = *(const float4*)&sm[S_VOL +
                        (dd * 5 + c + hh2) * 1280 + (k3 + ww) * 32 + cq * 4];
                    s.x += v.x; s.y += v.y; s.z += v.z; s.w += v.w;
                }
        s.x *= 0.125f; s.y *= 0.125f; s.z *= 0.125f; s.w *= 0.125f;
        *(float4*)&sm[S_POOL + c * 1404 + k3 * 36 + cq * 4] = s;
    }
    // MT[l*32+j] = M[j][l]
    for (int t = tid; t < 1024; t += 320)
        sm[S_MT + t] = sm[S_MS + (t & 31) * 33 + (t >> 5)];
    __syncthreads();

    // -------- Phase C: x matvec + A staging (vol region now dead) --------
    // A[c][t] = P[i,j] * tab[k1][t] * tab[k2b+c][t]
    for (int idx = tid; idx < 4096; idx += 320) {
        int c = idx >> 10;
        int t = idx & 1023;
        float a = 0.f;
        if (k2b + c < NP)
            a = sm[S_PS + (t & 31) * 33 + (t >> 5)]
              * g_tab[k1 * 1024 + t] * g_tab[(k2b + c) * 1024 + t];
        sm[S_A + idx] = a;
    }
    // x[c][j][k3] = sum_l MT[l][j] * pooled[c][k3][l]
    for (int job = tid; job < 1248; job += 320) {
        int c   = job / 312;
        int rem = job - c * 312;
        int k3  = rem >> 3;
        int jq  = rem & 7;
        float a0 = 0.f, a1 = 0.f, a2 = 0.f, a3 = 0.f;
        if (k2b + c < NP) {
#pragma unroll
            for (int l = 0; l < 32; l++) {
                float p = sm[S_POOL + c * 1404 + k3 * 36 + l];
                float4 m4 = *(const float4*)&sm[S_MT + l * 32 + jq * 4];
                a0 += p * m4.x; a1 += p * m4.y; a2 += p * m4.z; a3 += p * m4.w;
            }
        }
        sm[S_X + c * 1280 + (jq * 4 + 0) * 40 + k3] = a0;
        sm[S_X + c * 1280 + (jq * 4 + 1) * 40 + k3] = a1;
        sm[S_X + c * 1280 + (jq * 4 + 2) * 40 + k3] = a2;
        sm[S_X + c * 1280 + (jq * 4 + 3) * 40 + k3] = a3;
    }
    __syncthreads();

    // -------- Phase D: main contraction, j split across two groups --------
    const int jg  = tid >= 160;
    const int s   = tid - jg * 160;
    const int iq  = s & 7;
    const int k3p = s >> 3;              // 0..19 ; k3 = k3p*2 + t

    const ulonglong2* c3p[2];
#pragma unroll
    for (int t = 0; t < 2; t++) {
        int k3 = k3p * 2 + t; if (k3 > 38) k3 = 38;   // k3=39: x zeroed
        c3p[t] = (const ulonglong2*)(g_tab + k3 * 1024 + iq * 4);
    }
    const ulonglong2* ap = (const ulonglong2*)(sm + S_A + iq * 4);
    const float2*     xp = (const float2*)(sm + S_X);

    ull acc[4][2][2];
#pragma unroll
    for (int c = 0; c < 4; c++)
#pragma unroll
        for (int t = 0; t < 2; t++) { acc[c][t][0] = 0ull; acc[c][t][1] = 0ull; }

    const int j0 = jg * 16;
#pragma unroll 2
    for (int jj = 0; jj < 16; jj++) {
        int j = j0 + jj;
        ulonglong2 c3[2];
#pragma unroll
        for (int t = 0; t < 2; t++) c3[t] = c3p[t][j * 8];

        ulonglong2 a[4];
        float2     xv[4];
#pragma unroll
        for (int c = 0; c < 4; c++) {
            a[c]  = ap[c * 256 + j * 8];
            xv[c] = xp[(c * 1280 + j * 40) / 2 + k3p];
        }
#pragma unroll
        for (int c = 0; c < 4; c++) {
            ull xd0 = f2_pack(xv[c].x);
            ull xd1 = f2_pack(xv[c].y);
            acc[c][0][0] = f2_fma(f2_mul(a[c].x, xd0), c3[0].x, acc[c][0][0]);
            acc[c][0][1] = f2_fma(f2_mul(a[c].y, xd0), c3[0].y, acc[c][0][1]);
            acc[c][1][0] = f2_fma(f2_mul(a[c].x, xd1), c3[1].x, acc[c][1][0]);
            acc[c][1][1] = f2_fma(f2_mul(a[c].y, xd1), c3[1].y, acc[c][1][1]);
        }
    }

    // -------- Phase E: cross-group reduction + store --------
    ull* part = (ull*)(sm + S_PART);
    if (jg == 1) {
#pragma unroll
        for (int c = 0; c < 4; c++)
#pragma unroll
            for (int t = 0; t < 2; t++) {
                part[s * 17 + c * 4 + t * 2 + 0] = acc[c][t][0];
                part[s * 17 + c * 4 + t * 2 + 1] = acc[c][t][1];
            }
    }
    __syncthreads();
    if (jg == 0) {
#pragma unroll
        for (int c = 0; c < 4; c++) {
            if (k2b + c >= NP) continue;
#pragma unroll
            for (int t = 0; t < 2; t++) {
                int k3 = k3p * 2 + t;
                if (k3 >= NP) continue;
                ull lo = f2_add(acc[c][t][0], part[s * 17 + c * 4 + t * 2 + 0]);
                ull hi = f2_add(acc[c][t][1], part[s * 17 + c * 4 + t * 2 + 1]);
                float2 l2 = f2_unpack(lo);
                float2 h2 = f2_unpack(hi);
                int b = ((k1 * NP) + k2b + c) * NP + k3;
                *(float4*)&out[b * 32 + iq * 4] = make_float4(l2.x, l2.y, h2.x, h2.y);
            }
        }
    }
}

// ---------------------------------------------------------------------------
extern "C" void kernel_launch(void* const* d_in, const int* in_sizes, int n_in,
                              void* d_out, int out_size) {
    const float* vol = (const float*)d_in[0];
    const float* M   = (const float*)d_in[1];
    const float* P   = (const float*)d_in[2];
    float* out = (float*)d_out;

    static int attr_set = 0;
    if (!attr_set) {
        cudaFuncSetAttribute(k_fused, cudaFuncAttributeMaxDynamicSharedMemorySize,
                             SMEM_FLOATS * 4);
        attr_set = 1;
    }
    k_pre  <<<4, 256>>>();
    k_fused<<<dim3(10, 39), 320, SMEM_FLOATS * 4>>>(vol, M, P, out);
}